// round 13
// baseline (speedup 1.0000x reference)
#include <cuda_runtime.h>
#include <cuda_fp16.h>
#include <cstdint>

#define N_TOK 1024
#define DIM   2048
#define FDIM  5632
#define NEXP  8
#define RANK  16
#define LSCALE 2.0f

// ---------------- scratch (device globals; no allocations allowed) ----------------
__device__ __align__(256) __half g_W1h[FDIM * DIM];
__device__ __align__(256) __half g_W3h[FDIM * DIM];
__device__ __align__(256) __half g_W2h[DIM * FDIM];
__device__ __align__(256) __half g_xh[N_TOK * DIM];
__device__ __align__(256) __half g_A1h[128 * DIM];
__device__ __align__(256) __half g_A3h[128 * DIM];
__device__ __align__(256) __half g_smixh[N_TOK * FDIM];
__device__ __align__(256) __half g_sbufh[2 * N_TOK * FDIM];   // holds w_k * s
__device__ __align__(256) __half g_Y1h[N_TOK * FDIM];
__device__ __align__(256) __half g_Y3h[N_TOK * FDIM];
__device__ __align__(256) float g_l1[N_TOK * 128];
__device__ __align__(256) float g_l3[N_TOK * 128];
__device__ __align__(256) float g_psum[2 * N_TOK * DIM];
__device__ __align__(256) float g_l2acc[2 * N_TOK * RANK];
__device__ __align__(256) float g_topw[2 * N_TOK];
__device__ int   g_topi[2 * N_TOK];
__device__ int   g_cnt[NEXP];
__device__ int   g_list[NEXP * N_TOK];

// ---------------- utility ----------------
__device__ __forceinline__ void cp16(const __half* smem_dst, const __half* gsrc) {
    unsigned s = (unsigned)__cvta_generic_to_shared(smem_dst);
    asm volatile("cp.async.cg.shared.global [%0], [%1], 16;\n" :: "r"(s), "l"(gsrc));
}

#define MMA_F16(c, a, b) \
    asm volatile("mma.sync.aligned.m16n8k16.row.col.f32.f16.f16.f32 " \
        "{%0,%1,%2,%3}, {%4,%5,%6,%7}, {%8,%9}, {%0,%1,%2,%3};\n" \
        : "+f"((c)[0]), "+f"((c)[1]), "+f"((c)[2]), "+f"((c)[3]) \
        : "r"((a)[0]), "r"((a)[1]), "r"((a)[2]), "r"((a)[3]), "r"((b)[0]), "r"((b)[1]))

#define LDSM4(r0, r1, r2, r3, addr) \
    asm volatile("ldmatrix.sync.aligned.m8n8.x4.shared.b16 {%0,%1,%2,%3}, [%4];" \
        : "=r"(r0), "=r"(r1), "=r"(r2), "=r"(r3) : "r"(addr))

// ---- fp16 mma GEMM: CTA 128x128, warp 64x32, BK=64, 3-stage, 1 barrier/iter ----
#define GBM 128
#define GBN 128
#define GBK 64
#define GLDH 72                              // padded row: 72 halves = 144B
#define STG_H ((GBM + GBN) * GLDH)           // 18432 halves per stage
#define GEMM_SMEM (3 * STG_H * 2)            // 110592 B; 2 CTAs = 221KB <= 228KB/SM

__device__ __forceinline__ void gemm_core(const __half* __restrict__ Ag,
                                          const __half* __restrict__ Bg,
                                          float* __restrict__ Cg,
                                          __half* __restrict__ Ch,
                                          int Cld, int Kstride, int Klen) {
    extern __shared__ __align__(16) __half smh[];
    int tid = threadIdx.x;
    int wid = tid >> 5, lane = tid & 31;
    int wm = wid >> 2, wn = wid & 3;         // warp grid 2x4, warp tile 64x32
    int g = lane >> 2, t = lane & 3;
    int nkt = Klen / GBK;

    auto fill = [&](int kt, int slot) {
        __half* st = smh + slot * STG_H;
        const __half* acol = Ag + (size_t)kt * GBK;
        const __half* bcol = Bg + (size_t)kt * GBK;
        #pragma unroll
        for (int i = 0; i < 8; i++) {
            int id = i * 256 + tid;          // 16B chunk id, 0..2047
            int row = id >> 3, q = id & 7;
            const __half* src = (row < GBM)
                ? acol + (size_t)row * Kstride + q * 8
                : bcol + (size_t)(row - GBM) * Kstride + q * 8;
            cp16(st + row * GLDH + q * 8, src);
        }
        asm volatile("cp.async.commit_group;\n" ::: "memory");
    };

    fill(0, 0);
    if (nkt > 1) fill(1, 1);

    float c[4][4][4];
    #pragma unroll
    for (int mi = 0; mi < 4; mi++)
        #pragma unroll
        for (int ni = 0; ni < 4; ni++)
            #pragma unroll
            for (int q = 0; q < 4; q++) c[mi][ni][q] = 0.f;

    unsigned sbase32 = (unsigned)__cvta_generic_to_shared(smh);
    int mat = lane >> 3, r = lane & 7;
    unsigned aoff = (unsigned)((wm * 64 + (mat & 1) * 8 + r) * GLDH + (mat >> 1) * 8);
    unsigned boff = (unsigned)(GBM * GLDH + (wn * 32 + (mat >> 1) * 8 + r) * GLDH + (mat & 1) * 8);

    for (int kt = 0; kt < nkt; kt++) {
        if (kt + 1 < nkt) asm volatile("cp.async.wait_group 1;\n" ::: "memory");
        else              asm volatile("cp.async.wait_group 0;\n" ::: "memory");
        __syncthreads();                     // all warps done with compute(kt-1)
        if (kt + 2 < nkt) fill(kt + 2, (kt + 2) % 3);
        unsigned stg = sbase32 + (unsigned)((kt % 3) * STG_H) * 2u;
        unsigned abase = stg + aoff * 2u;
        unsigned bbase = stg + boff * 2u;
        #pragma unroll
        for (int s = 0; s < 4; s++) {
            unsigned ka = abase + (unsigned)(s * 16) * 2u;
            unsigned kb = bbase + (unsigned)(s * 16) * 2u;
            unsigned a[4][4], b[4][2];
            #pragma unroll
            for (int mi = 0; mi < 4; mi++)
                LDSM4(a[mi][0], a[mi][1], a[mi][2], a[mi][3],
                      ka + (unsigned)(mi * 16 * GLDH) * 2u);
            #pragma unroll
            for (int j = 0; j < 2; j++)
                LDSM4(b[2 * j][0], b[2 * j][1], b[2 * j + 1][0], b[2 * j + 1][1],
                      kb + (unsigned)(j * 16 * GLDH) * 2u);
            #pragma unroll
            for (int mi = 0; mi < 4; mi++)
                #pragma unroll
                for (int ni = 0; ni < 4; ni++)
                    MMA_F16(c[mi][ni], a[mi], b[ni]);
        }
    }

    if (Ch) {
        #pragma unroll
        for (int mi = 0; mi < 4; mi++) {
            int r0 = wm * 64 + mi * 16 + g;
            #pragma unroll
            for (int ni = 0; ni < 4; ni++) {
                int cc = wn * 32 + ni * 8 + 2 * t;
                *(__half2*)(Ch + (size_t)r0 * Cld + cc) = __floats2half2_rn(c[mi][ni][0], c[mi][ni][1]);
                *(__half2*)(Ch + (size_t)(r0 + 8) * Cld + cc) = __floats2half2_rn(c[mi][ni][2], c[mi][ni][3]);
            }
        }
    } else {
        #pragma unroll
        for (int mi = 0; mi < 4; mi++) {
            int r0 = wm * 64 + mi * 16 + g;
            #pragma unroll
            for (int ni = 0; ni < 4; ni++) {
                int cc = wn * 32 + ni * 8 + 2 * t;
                *(float2*)(Cg + (size_t)r0 * Cld + cc) = make_float2(c[mi][ni][0], c[mi][ni][1]);
                *(float2*)(Cg + (size_t)(r0 + 8) * Cld + cc) = make_float2(c[mi][ni][2], c[mi][ni][3]);
            }
        }
    }
}

// gemm1: x @ {W1(44 tiles), W3(44), A1(1), A3(1)}^T.  grid (8, 90)
__global__ __launch_bounds__(256, 2) void gemm_fused1_kernel() {
    int bm = blockIdx.x, by = blockIdx.y;
    const __half* Ag = g_xh + (size_t)bm * GBM * DIM;
    const __half* Bg;
    float* Cg = nullptr;
    __half* Ch = nullptr;
    int Cld;
    if (by < 44) {
        Bg = g_W1h + (size_t)by * GBN * DIM;
        Ch = g_Y1h + (size_t)bm * GBM * FDIM + by * GBN;
        Cld = FDIM;
    } else if (by < 88) {
        int b = by - 44;
        Bg = g_W3h + (size_t)b * GBN * DIM;
        Ch = g_Y3h + (size_t)bm * GBM * FDIM + b * GBN;
        Cld = FDIM;
    } else if (by == 88) {
        Bg = g_A1h;
        Cg = g_l1 + (size_t)bm * GBM * 128;
        Cld = 128;
    } else {
        Bg = g_A3h;
        Cg = g_l3 + (size_t)bm * GBM * 128;
        Cld = 128;
    }
    gemm_core(Ag, Bg, Cg, Ch, Cld, DIM, DIM);
}

// smix @ W2^T, split-K=2.  grid (8, 16, 2), K=2816 each
__global__ __launch_bounds__(256, 2) void gemm_w2_kernel() {
    int bm = blockIdx.x, bn = blockIdx.y, ks = blockIdx.z;
    const __half* Ag = g_smixh + (size_t)bm * GBM * FDIM + ks * 2816;
    const __half* Bg = g_W2h + (size_t)bn * GBN * FDIM + ks * 2816;
    float* Cg = g_psum + (size_t)ks * N_TOK * DIM + (size_t)bm * GBM * DIM + bn * GBN;
    gemm_core(Ag, Bg, Cg, nullptr, DIM, FDIM, 2816);
}

// ---- one-shot prep: fp32->fp16 for W1/W3/W2/x/A1/A3 + zero l2acc/cnt ----
#define NW4 (FDIM * DIM / 4)
#define NX4 (N_TOK * DIM / 4)
#define NA4 (128 * DIM / 4)
#define PREP_TOTAL (3 * NW4 + NX4 + 2 * NA4 + 2 * N_TOK * RANK / 4)

__global__ void prep_kernel(const float4* __restrict__ W1, const float4* __restrict__ W3,
                            const float4* __restrict__ W2, const float4* __restrict__ x,
                            const float4* __restrict__ A1, const float4* __restrict__ A3) {
    int i = blockIdx.x * blockDim.x + threadIdx.x;
    if (i >= PREP_TOTAL) return;
    const float4* s;
    __half* d;
    int j;
    if (i < NW4)                 { s = W1; d = g_W1h; j = i; }
    else if (i < 2 * NW4)        { s = W3; d = g_W3h; j = i - NW4; }
    else if (i < 3 * NW4)        { s = W2; d = g_W2h; j = i - 2 * NW4; }
    else if (i < 3 * NW4 + NX4)  { s = x;  d = g_xh;  j = i - 3 * NW4; }
    else if (i < 3 * NW4 + NX4 + NA4)     { s = A1; d = g_A1h; j = i - 3 * NW4 - NX4; }
    else if (i < 3 * NW4 + NX4 + 2 * NA4) { s = A3; d = g_A3h; j = i - 3 * NW4 - NX4 - NA4; }
    else {
        int j2 = i - (3 * NW4 + NX4 + 2 * NA4);
        ((float4*)g_l2acc)[j2] = make_float4(0.f, 0.f, 0.f, 0.f);
        if (j2 < NEXP) g_cnt[j2] = 0;
        return;
    }
    float4 v = s[j];
    __half2* dd = (__half2*)(d + (size_t)j * 4);
    dd[0] = __floats2half2_rn(v.x, v.y);
    dd[1] = __floats2half2_rn(v.z, v.w);
}

// ---------------- router (+ fused list build) ----------------
__global__ __launch_bounds__(256) void router_kernel(const float* __restrict__ x,
                                                     const float* __restrict__ gate,
                                                     float* __restrict__ logits_out) {
    int n = blockIdx.x;
    __shared__ float xs[DIM];
    __shared__ float lg[NEXP];
    for (int i = threadIdx.x; i < DIM; i += 256) xs[i] = x[(size_t)n * DIM + i];
    __syncthreads();
    int wid = threadIdx.x >> 5, lane = threadIdx.x & 31;
    const float* g = gate + (size_t)wid * DIM;
    float s = 0.f;
    for (int d = lane; d < DIM; d += 32) s += xs[d] * g[d];
    #pragma unroll
    for (int o = 16; o; o >>= 1) s += __shfl_xor_sync(0xffffffffu, s, o);
    if (lane == 0) lg[wid] = s;
    __syncthreads();
    if (threadIdx.x == 0) {
        #pragma unroll
        for (int e = 0; e < NEXP; e++) logits_out[n * NEXP + e] = lg[e];
        int i0 = 0; float v0 = lg[0];
        #pragma unroll
        for (int e = 1; e < NEXP; e++) if (lg[e] > v0) { v0 = lg[e]; i0 = e; }
        int i1 = -1; float v1 = -1e30f;
        #pragma unroll
        for (int e = 0; e < NEXP; e++) if (e != i0 && lg[e] > v1) { v1 = lg[e]; i1 = e; }
        float w0 = 1.f / (1.f + expf(v1 - v0));
        g_topi[2 * n] = i0; g_topi[2 * n + 1] = i1;
        g_topw[2 * n] = w0; g_topw[2 * n + 1] = 1.f - w0;
        int p0 = atomicAdd(&g_cnt[i0], 1);
        g_list[i0 * N_TOK + p0] = (n << 1);
        int p1 = atomicAdd(&g_cnt[i1], 1);
        g_list[i1 * N_TOK + p1] = (n << 1) | 1;
    }
}

// ---- fused LoRA-B + SwiGLU, token-sliced x8, prefetched; writes w_k * s (fp16) ----
__global__ __launch_bounds__(128) void expert_kernel(const float* __restrict__ B1,
                                                     const float* __restrict__ B3) {
    int e = blockIdx.y;
    int f0 = blockIdx.x * 128;
    int z = blockIdx.z;                      // token-group slice 0..7
    int f = threadIdx.x;
    __shared__ float B1s[16][128];
    __shared__ float B3s[16][128];
    __shared__ float lv[8][32];
    __shared__ int scode[8];
    {
        const float4* p1 = (const float4*)(B1 + (size_t)(e * FDIM + f0 + f) * RANK);
        const float4* p3 = (const float4*)(B3 + (size_t)(e * FDIM + f0 + f) * RANK);
        #pragma unroll
        for (int q = 0; q < 4; q++) {
            float4 v = p1[q];
            B1s[q * 4 + 0][f] = v.x; B1s[q * 4 + 1][f] = v.y;
            B1s[q * 4 + 2][f] = v.z; B1s[q * 4 + 3][f] = v.w;
            float4 u = p3[q];
            B3s[q * 4 + 0][f] = u.x; B3s[q * 4 + 1][f] = u.y;
            B3s[q * 4 + 2][f] = u.z; B3s[q * 4 + 3][f] = u.w;
        }
    }
    int cnt = g_cnt[e];
    for (int t0 = z * 8; t0 < cnt; t0 += 64) {
        int nt = (cnt - t0 < 8) ? (cnt - t0) : 8;
        __syncthreads();                     // protects B-tiles (1st iter) + lv reuse
        for (int idx = threadIdx.x; idx < nt * 32; idx += 128) {
            int ti = idx >> 5, r = idx & 31;
            int code = g_list[e * N_TOK + t0 + ti];
            int n = code >> 1;
            lv[ti][r] = (r < 16) ? g_l1[n * 128 + e * 16 + r]
                                 : g_l3[n * 128 + e * 16 + (r - 16)];
            if (r == 0) scode[ti] = code;
        }
        __syncthreads();
        float yb1[8], yb3[8], wv[8];
        int cd[8];
        for (int ti = 0; ti < nt; ti++) {
            cd[ti] = scode[ti];
            int n = cd[ti] >> 1;
            yb1[ti] = __half2float(g_Y1h[(size_t)n * FDIM + f0 + f]);
            yb3[ti] = __half2float(g_Y3h[(size_t)n * FDIM + f0 + f]);
            wv[ti] = g_topw[cd[ti]];
        }
        for (int ti = 0; ti < nt; ti++) {
            float h1 = 0.f, h3 = 0.f;
            #pragma unroll
            for (int r = 0; r < 16; r++) {
                h1 += lv[ti][r]      * B1s[r][f];
                h3 += lv[ti][16 + r] * B3s[r][f];
            }
            h1 = yb1[ti] + LSCALE * h1;
            h3 = yb3[ti] + LSCALE * h3;
            float sg = 1.f / (1.f + __expf(-h1));
            g_sbufh[(size_t)cd[ti] * FDIM + f0 + f] = __float2half_rn(wv[ti] * h1 * sg * h3);
        }
    }
}

// ---------------- s_mix = sw0 + sw1 (weights pre-folded), half2 ----------------
__global__ void mix_kernel() {
    int idx = blockIdx.x * blockDim.x + threadIdx.x;   // half2 index
    const int H2 = FDIM / 2;
    if (idx >= N_TOK * H2) return;
    int n = idx / H2;
    int j = idx - n * H2;
    const __half2* s0 = (const __half2*)(g_sbufh + (size_t)(2 * n) * FDIM);
    const __half2* s1 = (const __half2*)(g_sbufh + (size_t)(2 * n + 1) * FDIM);
    float2 a = __half22float2(s0[j]);
    float2 b = __half22float2(s1[j]);
    ((__half2*)(g_smixh + (size_t)n * FDIM))[j] = __floats2half2_rn(a.x + b.x, a.y + b.y);
}

// ---------------- l2acc[code,r] = sum_f sw * A2[e,r,f], token-sliced x16 ----------------
__global__ __launch_bounds__(128) void l2_kernel(const float* __restrict__ A2) {
    int e = blockIdx.y;
    int f0 = blockIdx.x * 512;
    int zslice = blockIdx.z;
    __shared__ float A2s[16][516];
    __shared__ float ss[512];
    for (int r = 0; r < 16; r++)
        for (int c = threadIdx.x; c < 512; c += 128)
            A2s[r][c] = A2[(size_t)(e * 16 + r) * FDIM + f0 + c];
    int rr = threadIdx.x >> 3, jj = threadIdx.x & 7;
    int cnt = g_cnt[e];
    for (int ti = zslice; ti < cnt; ti += 16) {
        int code = g_list[e * N_TOK + ti];
        __syncthreads();
        for (int c = threadIdx.x; c < 512; c += 128)
            ss[c] = __half2float(g_sbufh[(size_t)code * FDIM + f0 + c]);
        __syncthreads();
        float acc = 0.f;
        #pragma unroll 8
        for (int t = 0; t < 64; t++) {
            int c = t * 8 + jj;
            acc += ss[c] * A2s[rr][c];
        }
        acc += __shfl_xor_sync(0xffffffffu, acc, 1);
        acc += __shfl_xor_sync(0xffffffffu, acc, 2);
        acc += __shfl_xor_sync(0xffffffffu, acc, 4);
        if (jj == 0) atomicAdd(&g_l2acc[code * 16 + rr], acc);
    }
}

// ---------------- out = psum0 + psum1 + sum_k LSCALE*(l2 . B2) ----------------
__global__ __launch_bounds__(256) void final_kernel(const float* __restrict__ B2,
                                                    float* __restrict__ out) {
    int n = blockIdx.y;
    int d = blockIdx.x * 256 + threadIdx.x;
    __shared__ float lw[32];
    __shared__ int se[2];
    if (threadIdx.x < 32) {
        lw[threadIdx.x] = g_l2acc[n * 32 + threadIdx.x] * LSCALE;
        if (threadIdx.x < 2) se[threadIdx.x] = g_topi[2 * n + threadIdx.x];
    }
    __syncthreads();
    size_t id = (size_t)n * DIM + d;
    float o = g_psum[id] + g_psum[id + (size_t)N_TOK * DIM];
    #pragma unroll
    for (int k = 0; k < 2; k++) {
        const float4* b2 = (const float4*)(B2 + (size_t)(se[k] * DIM + d) * RANK);
        float a = 0.f;
        #pragma unroll
        for (int q = 0; q < 4; q++) {
            float4 v = b2[q];
            a += lw[k * 16 + q * 4 + 0] * v.x + lw[k * 16 + q * 4 + 1] * v.y
               + lw[k * 16 + q * 4 + 2] * v.z + lw[k * 16 + q * 4 + 3] * v.w;
        }
        o += a;
    }
    out[id] = o;
}

// ---------------- host ----------------
extern "C" void kernel_launch(void* const* d_in, const int* in_sizes, int n_in,
                              void* d_out, int out_size) {
    const float* x    = (const float*)d_in[0];
    const float* gate = (const float*)d_in[1];
    const float* W1   = (const float*)d_in[2];
    const float* W3   = (const float*)d_in[3];
    const float* W2   = (const float*)d_in[4];
    const float* A1   = (const float*)d_in[5];
    const float* B1   = (const float*)d_in[6];
    const float* A3   = (const float*)d_in[7];
    const float* B3   = (const float*)d_in[8];
    const float* A2   = (const float*)d_in[9];
    const float* B2   = (const float*)d_in[10];
    float* out = (float*)d_out;
    float* logits = out + (size_t)N_TOK * DIM;   // output order: (out, logits)

    cudaFuncSetAttribute(gemm_fused1_kernel, cudaFuncAttributeMaxDynamicSharedMemorySize, GEMM_SMEM);
    cudaFuncSetAttribute(gemm_w2_kernel,     cudaFuncAttributeMaxDynamicSharedMemorySize, GEMM_SMEM);

    // 8 launches, single stream. #4 = expert_kernel (profiled by ncu -s/-c)
    prep_kernel<<<(PREP_TOTAL + 255) / 256, 256>>>((const float4*)W1, (const float4*)W3,
                                                   (const float4*)W2, (const float4*)x,
                                                   (const float4*)A1, (const float4*)A3);
    router_kernel<<<N_TOK, 256>>>(x, gate, logits);
    gemm_fused1_kernel<<<dim3(8, 90), 256, GEMM_SMEM>>>();
    expert_kernel<<<dim3(FDIM / 128, NEXP, 8), 128>>>(B1, B3);
    mix_kernel<<<(N_TOK * FDIM / 2 + 255) / 256, 256>>>();
    l2_kernel<<<dim3(FDIM / 512, NEXP, 16), 128>>>(A2);
    gemm_w2_kernel<<<dim3(8, 16, 2), 256, GEMM_SMEM>>>();
    final_kernel<<<dim3(DIM / 256, N_TOK), 256>>>(B2, out);
}

// round 14
// speedup vs baseline: 1.2499x; 1.2499x over previous
#include <cuda_runtime.h>
#include <cuda_fp16.h>
#include <cstdint>

#define N_TOK 1024
#define DIM   2048
#define FDIM  5632
#define NEXP  8
#define RANK  16
#define LSCALE 2.0f

// ---------------- scratch (device globals; no allocations allowed) ----------------
__device__ __align__(256) __half g_W1h[FDIM * DIM];
__device__ __align__(256) __half g_W3h[FDIM * DIM];
__device__ __align__(256) __half g_W2h[DIM * FDIM];
__device__ __align__(256) __half g_xh[N_TOK * DIM];
__device__ __align__(256) __half g_A1h[128 * DIM];
__device__ __align__(256) __half g_A3h[128 * DIM];
__device__ __align__(256) __half g_smixh[N_TOK * FDIM];
__device__ __align__(256) __half g_sbufh[2 * N_TOK * FDIM];   // holds w_k * s
__device__ __align__(256) __half g_Y1h[N_TOK * FDIM];
__device__ __align__(256) __half g_Y3h[N_TOK * FDIM];
__device__ __align__(256) float g_l1[N_TOK * 128];
__device__ __align__(256) float g_l3[N_TOK * 128];
__device__ __align__(256) float g_psum[2 * N_TOK * DIM];
__device__ __align__(256) float g_l2acc[2 * N_TOK * RANK];
__device__ __align__(256) float g_topw[2 * N_TOK];
__device__ int   g_topi[2 * N_TOK];
__device__ int   g_cnt[NEXP];
__device__ int   g_list[NEXP * N_TOK];

// ---------------- utility ----------------
__device__ __forceinline__ void cp16(const __half* smem_dst, const __half* gsrc) {
    unsigned s = (unsigned)__cvta_generic_to_shared(smem_dst);
    asm volatile("cp.async.cg.shared.global [%0], [%1], 16;\n" :: "r"(s), "l"(gsrc));
}

#define MMA_F16(c, a, b) \
    asm volatile("mma.sync.aligned.m16n8k16.row.col.f32.f16.f16.f32 " \
        "{%0,%1,%2,%3}, {%4,%5,%6,%7}, {%8,%9}, {%0,%1,%2,%3};\n" \
        : "+f"((c)[0]), "+f"((c)[1]), "+f"((c)[2]), "+f"((c)[3]) \
        : "r"((a)[0]), "r"((a)[1]), "r"((a)[2]), "r"((a)[3]), "r"((b)[0]), "r"((b)[1]))

#define LDSM4(r0, r1, r2, r3, addr) \
    asm volatile("ldmatrix.sync.aligned.m8n8.x4.shared.b16 {%0,%1,%2,%3}, [%4];" \
        : "=r"(r0), "=r"(r1), "=r"(r2), "=r"(r3) : "r"(addr))

// ---- fp16 mma GEMM: CTA 128x128, warp 64x32, BK=64, 3-stage, 1 barrier/iter ----
#define GBM 128
#define GBN 128
#define GBK 64
#define GLDH 72                              // padded row: 72 halves = 144B
#define STG_H ((GBM + GBN) * GLDH)           // 18432 halves per stage
#define GEMM_SMEM (3 * STG_H * 2)            // 110592 B; 2 CTAs = 221KB <= 228KB/SM

__device__ __forceinline__ void gemm_core(const __half* __restrict__ Ag,
                                          const __half* __restrict__ Bg,
                                          float* __restrict__ Cg,
                                          __half* __restrict__ Ch,
                                          int Cld, int Kstride, int Klen) {
    extern __shared__ __align__(16) __half smh[];
    int tid = threadIdx.x;
    int wid = tid >> 5, lane = tid & 31;
    int wm = wid >> 2, wn = wid & 3;         // warp grid 2x4, warp tile 64x32
    int g = lane >> 2, t = lane & 3;
    int nkt = Klen / GBK;

    auto fill = [&](int kt, int slot) {
        __half* st = smh + slot * STG_H;
        const __half* acol = Ag + (size_t)kt * GBK;
        const __half* bcol = Bg + (size_t)kt * GBK;
        #pragma unroll
        for (int i = 0; i < 8; i++) {
            int id = i * 256 + tid;          // 16B chunk id, 0..2047
            int row = id >> 3, q = id & 7;
            const __half* src = (row < GBM)
                ? acol + (size_t)row * Kstride + q * 8
                : bcol + (size_t)(row - GBM) * Kstride + q * 8;
            cp16(st + row * GLDH + q * 8, src);
        }
        asm volatile("cp.async.commit_group;\n" ::: "memory");
    };

    fill(0, 0);
    if (nkt > 1) fill(1, 1);

    float c[4][4][4];
    #pragma unroll
    for (int mi = 0; mi < 4; mi++)
        #pragma unroll
        for (int ni = 0; ni < 4; ni++)
            #pragma unroll
            for (int q = 0; q < 4; q++) c[mi][ni][q] = 0.f;

    unsigned sbase32 = (unsigned)__cvta_generic_to_shared(smh);
    int mat = lane >> 3, r = lane & 7;
    unsigned aoff = (unsigned)((wm * 64 + (mat & 1) * 8 + r) * GLDH + (mat >> 1) * 8);
    unsigned boff = (unsigned)(GBM * GLDH + (wn * 32 + (mat >> 1) * 8 + r) * GLDH + (mat & 1) * 8);

    for (int kt = 0; kt < nkt; kt++) {
        if (kt + 1 < nkt) asm volatile("cp.async.wait_group 1;\n" ::: "memory");
        else              asm volatile("cp.async.wait_group 0;\n" ::: "memory");
        __syncthreads();                     // all warps done with compute(kt-1)
        if (kt + 2 < nkt) fill(kt + 2, (kt + 2) % 3);
        unsigned stg = sbase32 + (unsigned)((kt % 3) * STG_H) * 2u;
        unsigned abase = stg + aoff * 2u;
        unsigned bbase = stg + boff * 2u;
        #pragma unroll
        for (int s = 0; s < 4; s++) {
            unsigned ka = abase + (unsigned)(s * 16) * 2u;
            unsigned kb = bbase + (unsigned)(s * 16) * 2u;
            unsigned a[4][4], b[4][2];
            #pragma unroll
            for (int mi = 0; mi < 4; mi++)
                LDSM4(a[mi][0], a[mi][1], a[mi][2], a[mi][3],
                      ka + (unsigned)(mi * 16 * GLDH) * 2u);
            #pragma unroll
            for (int j = 0; j < 2; j++)
                LDSM4(b[2 * j][0], b[2 * j][1], b[2 * j + 1][0], b[2 * j + 1][1],
                      kb + (unsigned)(j * 16 * GLDH) * 2u);
            #pragma unroll
            for (int mi = 0; mi < 4; mi++)
                #pragma unroll
                for (int ni = 0; ni < 4; ni++)
                    MMA_F16(c[mi][ni], a[mi], b[ni]);
        }
    }

    if (Ch) {
        #pragma unroll
        for (int mi = 0; mi < 4; mi++) {
            int r0 = wm * 64 + mi * 16 + g;
            #pragma unroll
            for (int ni = 0; ni < 4; ni++) {
                int cc = wn * 32 + ni * 8 + 2 * t;
                *(__half2*)(Ch + (size_t)r0 * Cld + cc) = __floats2half2_rn(c[mi][ni][0], c[mi][ni][1]);
                *(__half2*)(Ch + (size_t)(r0 + 8) * Cld + cc) = __floats2half2_rn(c[mi][ni][2], c[mi][ni][3]);
            }
        }
    } else {
        #pragma unroll
        for (int mi = 0; mi < 4; mi++) {
            int r0 = wm * 64 + mi * 16 + g;
            #pragma unroll
            for (int ni = 0; ni < 4; ni++) {
                int cc = wn * 32 + ni * 8 + 2 * t;
                *(float2*)(Cg + (size_t)r0 * Cld + cc) = make_float2(c[mi][ni][0], c[mi][ni][1]);
                *(float2*)(Cg + (size_t)(r0 + 8) * Cld + cc) = make_float2(c[mi][ni][2], c[mi][ni][3]);
            }
        }
    }
}

// gemm1: x @ {W1(44 tiles), W3(44), A1(1), A3(1)}^T.  grid (8, 90)
__global__ __launch_bounds__(256, 2) void gemm_fused1_kernel() {
    int bm = blockIdx.x, by = blockIdx.y;
    const __half* Ag = g_xh + (size_t)bm * GBM * DIM;
    const __half* Bg;
    float* Cg = nullptr;
    __half* Ch = nullptr;
    int Cld;
    if (by < 44) {
        Bg = g_W1h + (size_t)by * GBN * DIM;
        Ch = g_Y1h + (size_t)bm * GBM * FDIM + by * GBN;
        Cld = FDIM;
    } else if (by < 88) {
        int b = by - 44;
        Bg = g_W3h + (size_t)b * GBN * DIM;
        Ch = g_Y3h + (size_t)bm * GBM * FDIM + b * GBN;
        Cld = FDIM;
    } else if (by == 88) {
        Bg = g_A1h;
        Cg = g_l1 + (size_t)bm * GBM * 128;
        Cld = 128;
    } else {
        Bg = g_A3h;
        Cg = g_l3 + (size_t)bm * GBM * 128;
        Cld = 128;
    }
    gemm_core(Ag, Bg, Cg, Ch, Cld, DIM, DIM);
}

// smix @ W2^T, split-K=2.  grid (8, 16, 2), K=2816 each
__global__ __launch_bounds__(256, 2) void gemm_w2_kernel() {
    int bm = blockIdx.x, bn = blockIdx.y, ks = blockIdx.z;
    const __half* Ag = g_smixh + (size_t)bm * GBM * FDIM + ks * 2816;
    const __half* Bg = g_W2h + (size_t)bn * GBN * FDIM + ks * 2816;
    float* Cg = g_psum + (size_t)ks * N_TOK * DIM + (size_t)bm * GBM * DIM + bn * GBN;
    gemm_core(Ag, Bg, Cg, nullptr, DIM, FDIM, 2816);
}

// ---- one-shot prep: fp32->fp16 for W1/W3/W2/x/A1/A3 + zero l2acc/cnt ----
#define NW4 (FDIM * DIM / 4)
#define NX4 (N_TOK * DIM / 4)
#define NA4 (128 * DIM / 4)
#define PREP_TOTAL (3 * NW4 + NX4 + 2 * NA4 + 2 * N_TOK * RANK / 4)

__global__ void prep_kernel(const float4* __restrict__ W1, const float4* __restrict__ W3,
                            const float4* __restrict__ W2, const float4* __restrict__ x,
                            const float4* __restrict__ A1, const float4* __restrict__ A3) {
    int i = blockIdx.x * blockDim.x + threadIdx.x;
    if (i >= PREP_TOTAL) return;
    const float4* s;
    __half* d;
    int j;
    if (i < NW4)                 { s = W1; d = g_W1h; j = i; }
    else if (i < 2 * NW4)        { s = W3; d = g_W3h; j = i - NW4; }
    else if (i < 3 * NW4)        { s = W2; d = g_W2h; j = i - 2 * NW4; }
    else if (i < 3 * NW4 + NX4)  { s = x;  d = g_xh;  j = i - 3 * NW4; }
    else if (i < 3 * NW4 + NX4 + NA4)     { s = A1; d = g_A1h; j = i - 3 * NW4 - NX4; }
    else if (i < 3 * NW4 + NX4 + 2 * NA4) { s = A3; d = g_A3h; j = i - 3 * NW4 - NX4 - NA4; }
    else {
        int j2 = i - (3 * NW4 + NX4 + 2 * NA4);
        ((float4*)g_l2acc)[j2] = make_float4(0.f, 0.f, 0.f, 0.f);
        if (j2 < NEXP) g_cnt[j2] = 0;
        return;
    }
    float4 v = s[j];
    __half2* dd = (__half2*)(d + (size_t)j * 4);
    dd[0] = __floats2half2_rn(v.x, v.y);
    dd[1] = __floats2half2_rn(v.z, v.w);
}

// ---------------- router (+ fused list build) ----------------
__global__ __launch_bounds__(256) void router_kernel(const float* __restrict__ x,
                                                     const float* __restrict__ gate,
                                                     float* __restrict__ logits_out) {
    int n = blockIdx.x;
    __shared__ float xs[DIM];
    __shared__ float lg[NEXP];
    for (int i = threadIdx.x; i < DIM; i += 256) xs[i] = x[(size_t)n * DIM + i];
    __syncthreads();
    int wid = threadIdx.x >> 5, lane = threadIdx.x & 31;
    const float* g = gate + (size_t)wid * DIM;
    float s = 0.f;
    for (int d = lane; d < DIM; d += 32) s += xs[d] * g[d];
    #pragma unroll
    for (int o = 16; o; o >>= 1) s += __shfl_xor_sync(0xffffffffu, s, o);
    if (lane == 0) lg[wid] = s;
    __syncthreads();
    if (threadIdx.x == 0) {
        #pragma unroll
        for (int e = 0; e < NEXP; e++) logits_out[n * NEXP + e] = lg[e];
        int i0 = 0; float v0 = lg[0];
        #pragma unroll
        for (int e = 1; e < NEXP; e++) if (lg[e] > v0) { v0 = lg[e]; i0 = e; }
        int i1 = -1; float v1 = -1e30f;
        #pragma unroll
        for (int e = 0; e < NEXP; e++) if (e != i0 && lg[e] > v1) { v1 = lg[e]; i1 = e; }
        float w0 = 1.f / (1.f + expf(v1 - v0));
        g_topi[2 * n] = i0; g_topi[2 * n + 1] = i1;
        g_topw[2 * n] = w0; g_topw[2 * n + 1] = 1.f - w0;
        int p0 = atomicAdd(&g_cnt[i0], 1);
        g_list[i0 * N_TOK + p0] = (n << 1);
        int p1 = atomicAdd(&g_cnt[i1], 1);
        g_list[i1 * N_TOK + p1] = (n << 1) | 1;
    }
}

// ---- fused LoRA-B + SwiGLU; B tiles in REGISTERS, 2 f-cols/thread ----
// grid (FDIM/256=22, NEXP, 8), block 128.  Per token: 32 broadcast LDS + 64 FMA.
__global__ __launch_bounds__(128) void expert_kernel(const float* __restrict__ B1,
                                                     const float* __restrict__ B3) {
    int e = blockIdx.y;
    int f0 = blockIdx.x * 256;
    int z = blockIdx.z;                      // token-group slice 0..7
    int f = threadIdx.x;
    int fa = f0 + f, fb = f0 + 128 + f;

    // B columns for this thread's two f-positions, in registers
    float B1a[16], B3a[16], B1b[16], B3b[16];
    {
        const float4* pa1 = (const float4*)(B1 + (size_t)(e * FDIM + fa) * RANK);
        const float4* pb1 = (const float4*)(B1 + (size_t)(e * FDIM + fb) * RANK);
        const float4* pa3 = (const float4*)(B3 + (size_t)(e * FDIM + fa) * RANK);
        const float4* pb3 = (const float4*)(B3 + (size_t)(e * FDIM + fb) * RANK);
        #pragma unroll
        for (int q = 0; q < 4; q++) {
            float4 v;
            v = pa1[q]; B1a[q*4+0]=v.x; B1a[q*4+1]=v.y; B1a[q*4+2]=v.z; B1a[q*4+3]=v.w;
            v = pb1[q]; B1b[q*4+0]=v.x; B1b[q*4+1]=v.y; B1b[q*4+2]=v.z; B1b[q*4+3]=v.w;
            v = pa3[q]; B3a[q*4+0]=v.x; B3a[q*4+1]=v.y; B3a[q*4+2]=v.z; B3a[q*4+3]=v.w;
            v = pb3[q]; B3b[q*4+0]=v.x; B3b[q*4+1]=v.y; B3b[q*4+2]=v.z; B3b[q*4+3]=v.w;
        }
    }

    __shared__ float lv[8][32];
    __shared__ int scode[8];
    int cnt = g_cnt[e];
    for (int t0 = z * 8; t0 < cnt; t0 += 64) {
        int nt = (cnt - t0 < 8) ? (cnt - t0) : 8;
        __syncthreads();                     // lv reuse
        for (int idx = threadIdx.x; idx < nt * 32; idx += 128) {
            int ti = idx >> 5, r = idx & 31;
            int code = g_list[e * N_TOK + t0 + ti];
            int n = code >> 1;
            lv[ti][r] = (r < 16) ? g_l1[n * 128 + e * 16 + r]
                                 : g_l3[n * 128 + e * 16 + (r - 16)];
            if (r == 0) scode[ti] = code;
        }
        __syncthreads();
        for (int ti = 0; ti < nt; ti++) {
            int code = scode[ti];
            int n = code >> 1;
            float w = g_topw[code];
            float y1a = __half2float(g_Y1h[(size_t)n * FDIM + fa]);
            float y1b = __half2float(g_Y1h[(size_t)n * FDIM + fb]);
            float y3a = __half2float(g_Y3h[(size_t)n * FDIM + fa]);
            float y3b = __half2float(g_Y3h[(size_t)n * FDIM + fb]);
            float h1a = 0.f, h1b = 0.f, h3a = 0.f, h3b = 0.f;
            #pragma unroll
            for (int r = 0; r < 16; r++) {
                float l1v = lv[ti][r];
                float l3v = lv[ti][16 + r];
                h1a += l1v * B1a[r];
                h1b += l1v * B1b[r];
                h3a += l3v * B3a[r];
                h3b += l3v * B3b[r];
            }
            h1a = y1a + LSCALE * h1a;
            h1b = y1b + LSCALE * h1b;
            h3a = y3a + LSCALE * h3a;
            h3b = y3b + LSCALE * h3b;
            float sa = h1a / (1.f + __expf(-h1a)) * h3a;
            float sb = h1b / (1.f + __expf(-h1b)) * h3b;
            g_sbufh[(size_t)code * FDIM + fa] = __float2half_rn(w * sa);
            g_sbufh[(size_t)code * FDIM + fb] = __float2half_rn(w * sb);
        }
    }
}

// ---------------- s_mix = sw0 + sw1 (weights pre-folded), half2 ----------------
__global__ void mix_kernel() {
    int idx = blockIdx.x * blockDim.x + threadIdx.x;   // half2 index
    const int H2 = FDIM / 2;
    if (idx >= N_TOK * H2) return;
    int n = idx / H2;
    int j = idx - n * H2;
    const __half2* s0 = (const __half2*)(g_sbufh + (size_t)(2 * n) * FDIM);
    const __half2* s1 = (const __half2*)(g_sbufh + (size_t)(2 * n + 1) * FDIM);
    float2 a = __half22float2(s0[j]);
    float2 b = __half22float2(s1[j]);
    ((__half2*)(g_smixh + (size_t)n * FDIM))[j] = __floats2half2_rn(a.x + b.x, a.y + b.y);
}

// ---- l2acc[code,r] = sum_f sw * A2[e,r,f]; A2 slice in REGISTERS ----
// grid (FDIM/256=22, NEXP, 16), block 128.  Per token: 32 LDS + 32 FMA.
__global__ __launch_bounds__(128) void l2_kernel(const float* __restrict__ A2) {
    int e = blockIdx.y;
    int f0 = blockIdx.x * 256;
    int zslice = blockIdx.z;
    int rr = threadIdx.x >> 3, jj = threadIdx.x & 7;

    float a2r[32];
    #pragma unroll
    for (int t = 0; t < 32; t++)
        a2r[t] = A2[(size_t)(e * 16 + rr) * FDIM + f0 + t * 8 + jj];

    __shared__ float ss[256];
    int cnt = g_cnt[e];
    for (int ti = zslice; ti < cnt; ti += 16) {
        int code = g_list[e * N_TOK + ti];
        __syncthreads();
        for (int c = threadIdx.x; c < 256; c += 128)
            ss[c] = __half2float(g_sbufh[(size_t)code * FDIM + f0 + c]);
        __syncthreads();
        float acc = 0.f;
        #pragma unroll
        for (int t = 0; t < 32; t++)
            acc += ss[t * 8 + jj] * a2r[t];
        acc += __shfl_xor_sync(0xffffffffu, acc, 1);
        acc += __shfl_xor_sync(0xffffffffu, acc, 2);
        acc += __shfl_xor_sync(0xffffffffu, acc, 4);
        if (jj == 0) atomicAdd(&g_l2acc[code * 16 + rr], acc);
    }
}

// ---------------- out = psum0 + psum1 + sum_k LSCALE*(l2 . B2) ----------------
__global__ __launch_bounds__(256) void final_kernel(const float* __restrict__ B2,
                                                    float* __restrict__ out) {
    int n = blockIdx.y;
    int d = blockIdx.x * 256 + threadIdx.x;
    __shared__ float lw[32];
    __shared__ int se[2];
    if (threadIdx.x < 32) {
        lw[threadIdx.x] = g_l2acc[n * 32 + threadIdx.x] * LSCALE;
        if (threadIdx.x < 2) se[threadIdx.x] = g_topi[2 * n + threadIdx.x];
    }
    __syncthreads();
    size_t id = (size_t)n * DIM + d;
    float o = g_psum[id] + g_psum[id + (size_t)N_TOK * DIM];
    #pragma unroll
    for (int k = 0; k < 2; k++) {
        const float4* b2 = (const float4*)(B2 + (size_t)(se[k] * DIM + d) * RANK);
        float a = 0.f;
        #pragma unroll
        for (int q = 0; q < 4; q++) {
            float4 v = b2[q];
            a += lw[k * 16 + q * 4 + 0] * v.x + lw[k * 16 + q * 4 + 1] * v.y
               + lw[k * 16 + q * 4 + 2] * v.z + lw[k * 16 + q * 4 + 3] * v.w;
        }
        o += a;
    }
    out[id] = o;
}

// ---------------- host ----------------
extern "C" void kernel_launch(void* const* d_in, const int* in_sizes, int n_in,
                              void* d_out, int out_size) {
    const float* x    = (const float*)d_in[0];
    const float* gate = (const float*)d_in[1];
    const float* W1   = (const float*)d_in[2];
    const float* W3   = (const float*)d_in[3];
    const float* W2   = (const float*)d_in[4];
    const float* A1   = (const float*)d_in[5];
    const float* B1   = (const float*)d_in[6];
    const float* A3   = (const float*)d_in[7];
    const float* B3   = (const float*)d_in[8];
    const float* A2   = (const float*)d_in[9];
    const float* B2   = (const float*)d_in[10];
    float* out = (float*)d_out;
    float* logits = out + (size_t)N_TOK * DIM;   // output order: (out, logits)

    cudaFuncSetAttribute(gemm_fused1_kernel, cudaFuncAttributeMaxDynamicSharedMemorySize, GEMM_SMEM);
    cudaFuncSetAttribute(gemm_w2_kernel,     cudaFuncAttributeMaxDynamicSharedMemorySize, GEMM_SMEM);

    // 8 launches, single stream. #4 = expert_kernel (profiled by ncu)
    prep_kernel<<<(PREP_TOTAL + 255) / 256, 256>>>((const float4*)W1, (const float4*)W3,
                                                   (const float4*)W2, (const float4*)x,
                                                   (const float4*)A1, (const float4*)A3);
    router_kernel<<<N_TOK, 256>>>(x, gate, logits);
    gemm_fused1_kernel<<<dim3(8, 90), 256, GEMM_SMEM>>>();
    expert_kernel<<<dim3(FDIM / 256, NEXP, 8), 128>>>(B1, B3);
    mix_kernel<<<(N_TOK * FDIM / 2 + 255) / 256, 256>>>();
    l2_kernel<<<dim3(FDIM / 256, NEXP, 16), 128>>>(A2);
    gemm_w2_kernel<<<dim3(8, 16, 2), 256, GEMM_SMEM>>>();
    final_kernel<<<dim3(DIM / 256, N_TOK), 256>>>(B2, out);
}